// round 15
// baseline (speedup 1.0000x reference)
#include <cuda_runtime.h>
#include <cuda_fp16.h>
#include <cstdint>

#define HIDDEN    450
#define ATOM_FDIM 35
#define MAX_NB    15

#define LDC     512          // fp32 activation stride (rows 2048B, 128B aligned)
#define KB_PAD  464          // 450 -> 29*16
#define KI_PAD  48           // 40  -> 3*16
#define KO_PAD  496          // 485 -> 31*16 (layout: [nei 450 | fatoms 35 | pad])
#define MB_PAD  40064        // 313*128
#define MA_PAD  20096        // 157*128
#define NW      512          // weight rows padded
#define N_MESS_MAX 16000

// tile: 128 (M) x 160 (N), grid.x = 3 -> N covered = 480 (>=456 needed)
#define BN      160
// smem stage layout (u32 offsets): Ahh[128x12] Bhh[160x12] Ax[128x20] Bx[160x20]
#define OFF_AHH 0
#define OFF_BHH 1536
#define OFF_AX  3456
#define OFF_BX  6016
#define STAGE_WORDS 9216
#define SMEM_BYTES  (3 * STAGE_WORDS * 4)     // 110592/CTA; 2 CTAs = 221KB <= 228KB
#define N_CHUNKS 1728

// ---------------- scratch (device globals; .bss zero => padding zero) --------
__device__ float    g_binput[(size_t)MB_PAD * LDC];
__device__ float    g_msgall[(size_t)(N_MESS_MAX + MB_PAD) * LDC];  // [tree | graph_message]
__device__ uint32_t g_neiHH[(size_t)MB_PAD * (KB_PAD/2)];
__device__ uint32_t g_neiX [(size_t)MB_PAD * KB_PAD];
__device__ uint32_t g_atHH [(size_t)MA_PAD * (KO_PAD/2)];
__device__ uint32_t g_atX  [(size_t)MA_PAD * KO_PAD];
__device__ uint32_t g_fbHH [(size_t)MB_PAD * (KI_PAD/2)];
__device__ uint32_t g_fbX  [(size_t)MB_PAD * KI_PAD];
__device__ uint32_t g_WiHH[NW * (KI_PAD/2)], g_WiX[NW * KI_PAD];
__device__ uint32_t g_WhHH[NW * (KB_PAD/2)], g_WhX[NW * KB_PAD];
__device__ uint32_t g_WoHH[NW * (KO_PAD/2)], g_WoX[NW * KO_PAD];

// ---------------- fp16 split helpers -----------------------------------------
__device__ __forceinline__ void split_h(float v, uint32_t& h, uint32_t& l) {
    __half hh = __float2half_rn(v);
    float  hf = __half2float(hh);
    __half ll = __float2half_rn(v - hf);
    h = (uint32_t)__half_as_ushort(hh);
    l = (uint32_t)__half_as_ushort(ll);
}

__device__ __forceinline__ void mma_f16(float* c, const uint32_t* a, uint32_t b0, uint32_t b1) {
    asm volatile(
        "mma.sync.aligned.m16n8k16.row.col.f32.f16.f16.f32 "
        "{%0,%1,%2,%3},{%4,%5,%6,%7},{%8,%9},{%0,%1,%2,%3};"
        : "+f"(c[0]), "+f"(c[1]), "+f"(c[2]), "+f"(c[3])
        : "r"(a[0]), "r"(a[1]), "r"(a[2]), "r"(a[3]), "r"(b0), "r"(b1));
}

// ---------------- tree copy into unified message table -----------------------
__global__ __launch_bounds__(256)
void copy_tree(const float* __restrict__ tree, float* __restrict__ msgall, int total)
{
    int i = blockIdx.x * blockDim.x + threadIdx.x;
    if (i >= total) return;
    int r = i / HIDDEN, c = i - r * HIDDEN;
    msgall[(size_t)r * LDC + c] = tree[i];
}

// ---------------- pre-split kernel ------------------------------------------
// SIDE 0 (A): x-pack = {lo16: hi, hi16: lo};  SIDE 1 (W): x-pack = {lo16: lo, hi16: hi}
template <int SIDE>
__global__ __launch_bounds__(256)
void split_pack(const float* __restrict__ src, int ld_src, int rows, int cols,
                uint32_t* __restrict__ hh, uint32_t* __restrict__ xx,
                int ldx, int dstk0 /* even */)
{
    const int npair = (cols + 1) >> 1;
    int i = blockIdx.x * blockDim.x + threadIdx.x;
    if (i >= rows * npair) return;
    int r = i / npair, jj = i - r * npair;
    int k0 = 2 * jj, k1 = k0 + 1;
    float v0 = src[(size_t)r * ld_src + k0];
    float v1 = (k1 < cols) ? src[(size_t)r * ld_src + k1] : 0.f;
    uint32_t h0, l0, h1, l1;
    split_h(v0, h0, l0);
    split_h(v1, h1, l1);
    const int ldh = ldx >> 1;
    hh[(size_t)r * ldh + (dstk0 >> 1) + jj] = h0 | (h1 << 16);
    size_t ox = (size_t)r * ldx + dstk0 + k0;
    if (SIDE == 0) {
        xx[ox]     = h0 | (l0 << 16);
        xx[ox + 1] = h1 | (l1 << 16);
    } else {
        xx[ox]     = l0 | (h0 << 16);
        xx[ox + 1] = l1 | (h1 << 16);
    }
}

// ---------------- gather + split (branchless, float4, 2 rows/block) ----------
__global__ __launch_bounds__(256)
void gather_split(const int* __restrict__ graph, const float* __restrict__ msgall,
                  uint32_t* __restrict__ hh, uint32_t* __restrict__ xx,
                  int ldx, int nrows)
{
    const int half = threadIdx.x >> 7;
    const int b = blockIdx.x * 2 + half;
    const int t = threadIdx.x & 127;
    __shared__ const float* rows[2][MAX_NB];
    if (t < MAX_NB && b < nrows) {
        int id = graph[(size_t)b * MAX_NB + t];
        rows[half][t] = msgall + (size_t)id * LDC;
    }
    __syncthreads();
    if (b >= nrows) return;

    const float* rp[MAX_NB];
#pragma unroll
    for (int nb = 0; nb < MAX_NB; nb++) rp[nb] = rows[half][nb];

    const int ldh = ldx >> 1;
    if (t < 112) {                               // cols 4t .. 4t+3
        float4 acc = make_float4(0.f, 0.f, 0.f, 0.f);
#pragma unroll
        for (int nb = 0; nb < MAX_NB; nb++) {
            float4 v = ((const float4*)rp[nb])[t];
            acc.x += v.x; acc.y += v.y; acc.z += v.z; acc.w += v.w;
        }
        uint32_t h0, l0, h1, l1, h2, l2, h3, l3;
        split_h(acc.x, h0, l0); split_h(acc.y, h1, l1);
        split_h(acc.z, h2, l2); split_h(acc.w, h3, l3);
        *(uint2*)(hh + (size_t)b * ldh + 2 * t) =
            make_uint2(h0 | (h1 << 16), h2 | (h3 << 16));
        *(uint4*)(xx + (size_t)b * ldx + 4 * t) =
            make_uint4(h0 | (l0 << 16), h1 | (l1 << 16),
                       h2 | (l2 << 16), h3 | (l3 << 16));
    } else if (t == 112) {                        // cols 448, 449
        float2 acc = make_float2(0.f, 0.f);
#pragma unroll
        for (int nb = 0; nb < MAX_NB; nb++) {
            float2 v = ((const float2*)rp[nb])[224];
            acc.x += v.x; acc.y += v.y;
        }
        uint32_t h0, l0, h1, l1;
        split_h(acc.x, h0, l0); split_h(acc.y, h1, l1);
        hh[(size_t)b * ldh + 224] = h0 | (h1 << 16);
        *(uint2*)(xx + (size_t)b * ldx + 448) =
            make_uint2(h0 | (l0 << 16), h1 | (l1 << 16));
    }
}

// ---------------- pipelined fp16 3-term GEMM (128x160, 3-stage, 1 barrier) ---
// MODE 0: C = t, C2 = relu(t);  MODE 1: C = relu(t + biasM);  MODE 2: relu(t + biasV[n])
template <int MODE>
__global__ __launch_bounds__(256, 2)
void mma_gemm(const uint32_t* __restrict__ AHH, const uint32_t* __restrict__ AX,
              const uint32_t* __restrict__ WHH, const uint32_t* __restrict__ WX,
              int ldx, int nK,
              const float* __restrict__ biasM, const float* __restrict__ biasV,
              float* __restrict__ C, float* __restrict__ C2)
{
    extern __shared__ uint32_t sm[];
    const unsigned sbase = (unsigned)__cvta_generic_to_shared(sm);
    const int ldh = ldx >> 1;

    const int tid  = threadIdx.x;
    const int lane = tid & 31;
    const int wid  = tid >> 5;
    const int wm   = wid & 3;          // 4 warps along M (32 rows each)
    const int wn   = wid >> 2;         // 2 warps along N (80 cols each)
    const int row0 = blockIdx.y * 128;
    const int col0 = blockIdx.x * BN;

    float acc[2][10][4];
#pragma unroll
    for (int a = 0; a < 2; a++)
#pragma unroll
        for (int b = 0; b < 10; b++)
#pragma unroll
            for (int q = 0; q < 4; q++) acc[a][b][q] = 0.f;

    auto issue = [&](int stage, int kt) {
        const unsigned sb = sbase + stage * (STAGE_WORDS * 4);
        const int kh0 = kt * 8;
        const int kx0 = kt * 16;
#pragma unroll
        for (int i = 0; i < 7; i++) {
            int p = i * 256 + tid;
            if (p >= N_CHUNKS) break;
            const uint32_t* g;
            unsigned d;
            if (p < 256) {                     // Ahh: 128 rows x 2 chunks
                int row = p >> 1, q = p & 1;
                g = AHH + (size_t)(row0 + row) * ldh + kh0 + q * 4;
                d = sb + (unsigned)(OFF_AHH + row * 12 + q * 4) * 4u;
            } else if (p < 576) {              // Bhh: 160 rows x 2 chunks
                int pp = p - 256;
                int row = pp >> 1, q = pp & 1;
                g = WHH + (size_t)(col0 + row) * ldh + kh0 + q * 4;
                d = sb + (unsigned)(OFF_BHH + row * 12 + q * 4) * 4u;
            } else if (p < 1088) {             // Ax: 128 rows x 4 chunks
                int pp = p - 576;
                int row = pp >> 2, q = pp & 3;
                g = AX + (size_t)(row0 + row) * ldx + kx0 + q * 4;
                d = sb + (unsigned)(OFF_AX + row * 20 + q * 4) * 4u;
            } else {                           // Bx: 160 rows x 4 chunks
                int pp = p - 1088;
                int row = pp >> 2, q = pp & 3;
                g = WX + (size_t)(col0 + row) * ldx + kx0 + q * 4;
                d = sb + (unsigned)(OFF_BX + row * 20 + q * 4) * 4u;
            }
            asm volatile("cp.async.cg.shared.global [%0], [%1], 16;\n" :: "r"(d), "l"(g));
        }
        asm volatile("cp.async.commit_group;\n");
    };

    issue(0, 0);
    issue(1, 1);          // nK >= 3 for all layers

    for (int kt = 0; kt < nK; kt++) {
        asm volatile("cp.async.wait_group 1;\n");   // stage kt resident
        __syncthreads();                            // all warps done with stage kt-1

        if (kt + 2 < nK) issue((kt + 2) % 3, kt + 2);
        else             asm volatile("cp.async.commit_group;\n");

        const uint32_t* S = sm + (kt % 3) * STAGE_WORDS;
        const uint32_t* sAhh = S + OFF_AHH;
        const uint32_t* sBhh = S + OFF_BHH;
        const uint32_t* sAx  = S + OFF_AX;
        const uint32_t* sBx  = S + OFF_BX;

        // ---- hh: one k16 MMA covers all 16 original k
        {
            const int kc = lane & 3;
            uint32_t aH[2][4];
#pragma unroll
            for (int mt = 0; mt < 2; mt++) {
                int r = wm * 32 + mt * 16 + (lane >> 2);
                const uint32_t* p = sAhh + r * 12 + kc;
                aH[mt][0] = p[0]; aH[mt][1] = p[96]; aH[mt][2] = p[4]; aH[mt][3] = p[100];
            }
#pragma unroll
            for (int nt = 0; nt < 10; nt++) {
                int n = wn * 80 + nt * 8 + (lane >> 2);
                const uint32_t* p = sBhh + n * 12 + kc;
                uint32_t b0 = p[0], b1 = p[4];
#pragma unroll
                for (int mt = 0; mt < 2; mt++)
                    mma_f16(acc[mt][nt], aH[mt], b0, b1);
            }
        }

        // ---- cross: two k16 MMAs (8 original k each)
#pragma unroll
        for (int ks = 0; ks < 2; ks++) {
            const int kc = ks * 8 + (lane & 3);
            uint32_t aX[2][4];
#pragma unroll
            for (int mt = 0; mt < 2; mt++) {
                int r = wm * 32 + mt * 16 + (lane >> 2);
                const uint32_t* p = sAx + r * 20 + kc;
                aX[mt][0] = p[0]; aX[mt][1] = p[160]; aX[mt][2] = p[4]; aX[mt][3] = p[164];
            }
#pragma unroll
            for (int nt = 0; nt < 10; nt++) {
                int n = wn * 80 + nt * 8 + (lane >> 2);
                const uint32_t* p = sBx + n * 20 + kc;
                uint32_t b0 = p[0], b1 = p[4];
#pragma unroll
                for (int mt = 0; mt < 2; mt++)
                    mma_f16(acc[mt][nt], aX[mt], b0, b1);
            }
        }
    }

    // epilogue (rows padded; cols < 480 <= LDC, padded cols harmless)
#pragma unroll
    for (int mt = 0; mt < 2; mt++) {
#pragma unroll
        for (int h = 0; h < 2; h++) {
            int r = row0 + wm * 32 + mt * 16 + (lane >> 2) + h * 8;
#pragma unroll
            for (int nt = 0; nt < 10; nt++) {
                int c = col0 + wn * 80 + nt * 8 + 2 * (lane & 3);
                float x = acc[mt][nt][h * 2 + 0];
                float y = acc[mt][nt][h * 2 + 1];
                size_t o = (size_t)r * LDC + c;
                if (MODE == 0) {
                    *(float2*)(C + o)  = make_float2(x, y);
                    *(float2*)(C2 + o) = make_float2(x > 0.f ? x : 0.f, y > 0.f ? y : 0.f);
                } else if (MODE == 1) {
                    float2 bm = *(const float2*)(biasM + o);
                    x += bm.x; y += bm.y;
                    *(float2*)(C + o) = make_float2(x > 0.f ? x : 0.f, y > 0.f ? y : 0.f);
                } else {
                    x += (c     < HIDDEN) ? biasV[c]     : 0.f;
                    y += (c + 1 < HIDDEN) ? biasV[c + 1] : 0.f;
                    *(float2*)(C + o) = make_float2(x > 0.f ? x : 0.f, y > 0.f ? y : 0.f);
                }
            }
        }
    }
}

// ---------------- per-molecule mean -----------------------------------------
__global__ __launch_bounds__(256)
void mol_mean_kernel(const float* __restrict__ ah, const int* __restrict__ mol_ids,
                     int n_atoms, float* __restrict__ out)
{
    const int m = blockIdx.x;
    __shared__ int s_start, s_end;
    if (threadIdx.x == 0) {
        int lo = 0, hi = n_atoms;
        while (lo < hi) { int mid = (lo + hi) >> 1; if (mol_ids[mid] <  m) lo = mid + 1; else hi = mid; }
        s_start = lo;
        lo = 0; hi = n_atoms;
        while (lo < hi) { int mid = (lo + hi) >> 1; if (mol_ids[mid] <= m) lo = mid + 1; else hi = mid; }
        s_end = lo;
    }
    __syncthreads();
    const int start = s_start;
    const int cnt   = s_end - s_start;
    const float inv = cnt > 0 ? 1.f / (float)cnt : 0.f;

    for (int h = threadIdx.x; h < HIDDEN; h += blockDim.x) {
        float s = 0.f;
        for (int a = 0; a < cnt; a++)
            s += ah[(size_t)(start + a) * LDC + h];
        out[(size_t)m * HIDDEN + h] = s * inv;
    }
}

// ---------------- launch ----------------------------------------------------
extern "C" void kernel_launch(void* const* d_in, const int* in_sizes, int n_in,
                              void* d_out, int out_size)
{
    const float* fatoms  = (const float*)d_in[0];
    const float* fbonds  = (const float*)d_in[1];
    const int*   agraph  = (const int*)d_in[2];
    const int*   bgraph  = (const int*)d_in[3];
    const int*   mol_ids = (const int*)d_in[4];
    const float* tree    = (const float*)d_in[6];
    const float* W_i     = (const float*)d_in[7];
    const float* W_h     = (const float*)d_in[8];
    const float* W_o     = (const float*)d_in[9];
    const float* b_o     = (const float*)d_in[10];
    float* out = (float*)d_out;

    const int n_atoms = in_sizes[0] / ATOM_FDIM;
    const int n_bonds = in_sizes[1] / (ATOM_FDIM + 5);
    const int n_mess  = in_sizes[6] / HIDDEN;
    const int n_mols  = out_size / HIDDEN;
    const int IN_FDIM = ATOM_FDIM + 5;       // 40
    const int OUT_K   = ATOM_FDIM + HIDDEN;  // 485 (src W_o ld)

    float *binput, *msgall;
    uint32_t *neiHH, *neiX, *atHH, *atX, *fbHH, *fbX;
    uint32_t *WiHH, *WiX, *WhHH, *WhX, *WoHH, *WoX;
    cudaGetSymbolAddress((void**)&binput, g_binput);
    cudaGetSymbolAddress((void**)&msgall, g_msgall);
    cudaGetSymbolAddress((void**)&neiHH,  g_neiHH);
    cudaGetSymbolAddress((void**)&neiX,   g_neiX);
    cudaGetSymbolAddress((void**)&atHH,   g_atHH);
    cudaGetSymbolAddress((void**)&atX,    g_atX);
    cudaGetSymbolAddress((void**)&fbHH,   g_fbHH);
    cudaGetSymbolAddress((void**)&fbX,    g_fbX);
    cudaGetSymbolAddress((void**)&WiHH,   g_WiHH);
    cudaGetSymbolAddress((void**)&WiX,    g_WiX);
    cudaGetSymbolAddress((void**)&WhHH,   g_WhHH);
    cudaGetSymbolAddress((void**)&WhX,    g_WhX);
    cudaGetSymbolAddress((void**)&WoHH,   g_WoHH);
    cudaGetSymbolAddress((void**)&WoX,    g_WoX);

    float* gmsg = msgall + (size_t)n_mess * LDC;   // graph_message lives inside msgall

    cudaFuncSetAttribute(mma_gemm<0>, cudaFuncAttributeMaxDynamicSharedMemorySize, SMEM_BYTES);
    cudaFuncSetAttribute(mma_gemm<1>, cudaFuncAttributeMaxDynamicSharedMemorySize, SMEM_BYTES);
    cudaFuncSetAttribute(mma_gemm<2>, cudaFuncAttributeMaxDynamicSharedMemorySize, SMEM_BYTES);

    dim3 blk(256);
    const int mb = (n_bonds + 127) / 128;   // 313
    const int ma = (n_atoms + 127) / 128;   // 157
    dim3 grid_b(3, mb), grid_a(3, ma);      // 3 x 160 = 480 cols

    // ---- one-time: tree into unified message table
    copy_tree<<<(n_mess * HIDDEN + 255) / 256, blk>>>(tree, msgall, n_mess * HIDDEN);

    // ---- pre-split inputs (SIDE 0) & weights (SIDE 1)
    split_pack<0><<<(n_bonds * ((IN_FDIM + 1) / 2) + 255) / 256, blk>>>(
        fbonds, IN_FDIM, n_bonds, IN_FDIM, fbHH, fbX, KI_PAD, 0);
    split_pack<1><<<(HIDDEN * ((IN_FDIM + 1) / 2) + 255) / 256, blk>>>(
        W_i, IN_FDIM, HIDDEN, IN_FDIM, WiHH, WiX, KI_PAD, 0);
    split_pack<1><<<(HIDDEN * ((HIDDEN + 1) / 2) + 255) / 256, blk>>>(
        W_h, HIDDEN, HIDDEN, HIDDEN, WhHH, WhX, KB_PAD, 0);
    // W_o permuted: [nei 450 | fatoms 35]
    split_pack<1><<<(HIDDEN * ((HIDDEN + 1) / 2) + 255) / 256, blk>>>(
        W_o + ATOM_FDIM, OUT_K, HIDDEN, HIDDEN, WoHH, WoX, KO_PAD, 0);
    split_pack<1><<<(HIDDEN * ((ATOM_FDIM + 1) / 2) + 255) / 256, blk>>>(
        W_o, OUT_K, HIDDEN, ATOM_FDIM, WoHH, WoX, KO_PAD, HIDDEN);
    // fatoms at k-offset 450
    split_pack<0><<<(n_atoms * ((ATOM_FDIM + 1) / 2) + 255) / 256, blk>>>(
        fatoms, ATOM_FDIM, n_atoms, ATOM_FDIM, atHH, atX, KO_PAD, HIDDEN);

    // ---- init layer: binput = fbonds @ W_i^T ; graph_message = relu(binput)
    mma_gemm<0><<<grid_b, blk, SMEM_BYTES>>>(fbHH, fbX, WiHH, WiX, KI_PAD, KI_PAD / 16,
                                             nullptr, nullptr, binput, gmsg);

    // ---- 5 message-passing steps
    for (int it = 0; it < 5; it++) {
        gather_split<<<(n_bonds + 1) / 2, blk>>>(bgraph, msgall, neiHH, neiX, KB_PAD, n_bonds);
        mma_gemm<1><<<grid_b, blk, SMEM_BYTES>>>(neiHH, neiX, WhHH, WhX, KB_PAD, KB_PAD / 16,
                                                 binput, nullptr, gmsg, nullptr);
    }

    // ---- atom aggregation (nei at k 0..449) + output layer
    gather_split<<<(n_atoms + 1) / 2, blk>>>(agraph, msgall, atHH, atX, KO_PAD, n_atoms);
    mma_gemm<2><<<grid_a, blk, SMEM_BYTES>>>(atHH, atX, WoHH, WoX, KO_PAD, KO_PAD / 16,
                                             nullptr, b_o, binput, nullptr);

    // ---- per-molecule mean (atom_hiddens reuses g_binput)
    mol_mean_kernel<<<n_mols, blk>>>(binput, mol_ids, n_atoms, out);
}

// round 16
// speedup vs baseline: 1.1889x; 1.1889x over previous
#include <cuda_runtime.h>
#include <cuda_fp16.h>
#include <cstdint>

#define HIDDEN    450
#define ATOM_FDIM 35
#define MAX_NB    15

#define LDC     512          // fp32 activation stride
#define MB_PAD  40064        // 313*128
#define MA_PAD  20096        // 157*128
#define MB_T    313          // row blocks (bonds)
#define MA_T    157          // row blocks (atoms)
#define NCB     3            // col blocks (3 x 160 = 480 >= 456)
#define KT_B    29           // ktiles, hidden K (464/16)
#define KT_I    3            // ktiles, input K (48/16)
#define KT_O    31           // ktiles, output K (496/16)

#define BN      160
// tile-major images: A image 4096 u32 = Ahh[128][12] | Ax[128][20]
//                    W image 5120 u32 = Bhh[160][12] | Bx[160][20]
#define A_IMG   4096
#define W_IMG   5120
#define STAGE_WORDS 9216                       // A_IMG + W_IMG
#define STAGE_BYTES (STAGE_WORDS * 4)          // 36864
#define SMEM_BYTES  (3 * STAGE_BYTES + 64)     // 3 stages + mbarriers

// ---------------- scratch (device globals; .bss zero => padding zero) --------
__device__ float g_binput[(size_t)MB_PAD * LDC];
__device__ float g_gmsg  [(size_t)MB_PAD * LDC];
__device__ __align__(128) uint32_t g_neiI[(size_t)MB_T * KT_B * A_IMG];
__device__ __align__(128) uint32_t g_atI [(size_t)MA_T * KT_O * A_IMG];
__device__ __align__(128) uint32_t g_fbI [(size_t)MB_T * KT_I * A_IMG];
__device__ __align__(128) uint32_t g_WiI [NCB * KT_I * W_IMG];
__device__ __align__(128) uint32_t g_WhI [NCB * KT_B * W_IMG];
__device__ __align__(128) uint32_t g_WoI [NCB * KT_O * W_IMG];

// ---------------- fp16 split helpers -----------------------------------------
__device__ __forceinline__ void split_h(float v, uint32_t& h, uint32_t& l) {
    __half hh = __float2half_rn(v);
    float  hf = __half2float(hh);
    __half ll = __float2half_rn(v - hf);
    h = (uint32_t)__half_as_ushort(hh);
    l = (uint32_t)__half_as_ushort(ll);
}

__device__ __forceinline__ void mma_f16(float* c, const uint32_t* a, uint32_t b0, uint32_t b1) {
    asm volatile(
        "mma.sync.aligned.m16n8k16.row.col.f32.f16.f16.f32 "
        "{%0,%1,%2,%3},{%4,%5,%6,%7},{%8,%9},{%0,%1,%2,%3};"
        : "+f"(c[0]), "+f"(c[1]), "+f"(c[2]), "+f"(c[3])
        : "r"(a[0]), "r"(a[1]), "r"(a[2]), "r"(a[3]), "r"(b0), "r"(b1));
}

__device__ __forceinline__ void mbar_wait(unsigned bar, unsigned phase) {
    asm volatile(
        "{\n\t.reg .pred P;\n\t"
        "W_%=:\n\t"
        "mbarrier.try_wait.parity.acquire.cta.shared::cta.b64 P, [%0], %1;\n\t"
        "@!P bra W_%=;\n\t"
        "}" :: "r"(bar), "r"(phase) : "memory");
}

// ---------------- pre-split into tile-major images ---------------------------
// SIDE 0 (A image): x-pack = {lo16: hi, hi16: lo}, rows/blk 128
// SIDE 1 (W image): x-pack = {lo16: lo, hi16: hi}, rows/blk 160
template <int SIDE>
__global__ __launch_bounds__(256)
void split_pack(const float* __restrict__ src, int ld_src, int rows, int cols,
                uint32_t* __restrict__ img, int nKt, int dstk0 /* even */)
{
    const int npair = (cols + 1) >> 1;
    int i = blockIdx.x * blockDim.x + threadIdx.x;
    if (i >= rows * npair) return;
    int r = i / npair, jj = i - r * npair;
    int k0 = 2 * jj, k1 = k0 + 1;
    float v0 = src[(size_t)r * ld_src + k0];
    float v1 = (k1 < cols) ? src[(size_t)r * ld_src + k1] : 0.f;
    uint32_t h0, l0, h1, l1;
    split_h(v0, h0, l0);
    split_h(v1, h1, l1);
    int kg = dstk0 + k0;           // global even k
    int kt = kg >> 4, w = kg & 15;
    if (SIDE == 0) {
        int rb = r >> 7, rr = r & 127;
        size_t base = ((size_t)rb * nKt + kt) * A_IMG;
        img[base + rr * 12 + (w >> 1)]        = h0 | (h1 << 16);
        img[base + 1536 + rr * 20 + w]        = h0 | (l0 << 16);
        img[base + 1536 + rr * 20 + w + 1]    = h1 | (l1 << 16);
    } else {
        int cb = r / BN, rr = r - cb * BN;
        size_t base = ((size_t)cb * nKt + kt) * W_IMG;
        img[base + rr * 12 + (w >> 1)]        = h0 | (h1 << 16);
        img[base + 1920 + rr * 20 + w]        = l0 | (h0 << 16);
        img[base + 1920 + rr * 20 + w + 1]    = l1 | (h1 << 16);
    }
}

// ---------------- gather + split into A image --------------------------------
__global__ __launch_bounds__(256)
void gather_split(const int* __restrict__ graph,
                  const float* __restrict__ tree, int n_mess,
                  const float* __restrict__ gmsg,
                  uint32_t* __restrict__ img, int nKt)
{
    const int b = blockIdx.x;
    __shared__ const float* rows[MAX_NB];
    if (threadIdx.x < MAX_NB) {
        int id = graph[(size_t)b * MAX_NB + threadIdx.x];
        rows[threadIdx.x] = (id < n_mess) ? (tree + (size_t)id * HIDDEN)
                                          : (gmsg + (size_t)(id - n_mess) * LDC);
    }
    __syncthreads();
    const int t = threadIdx.x;
    if (t < HIDDEN / 2) {
        float2 acc = make_float2(0.f, 0.f);
#pragma unroll
        for (int nb = 0; nb < MAX_NB; nb++) {
            float2 v = ((const float2*)rows[nb])[t];
            acc.x += v.x; acc.y += v.y;
        }
        uint32_t h0, l0, h1, l1;
        split_h(acc.x, h0, l0);
        split_h(acc.y, h1, l1);
        int kt = t >> 3;                 // ktile of k=2t
        int hw = t & 7;                  // hh word
        int xw = (t & 7) * 2;            // x word
        size_t base = ((size_t)(b >> 7) * nKt + kt) * A_IMG;
        int rr = b & 127;
        img[base + rr * 12 + hw]           = h0 | (h1 << 16);
        img[base + 1536 + rr * 20 + xw]    = h0 | (l0 << 16);
        img[base + 1536 + rr * 20 + xw + 1] = h1 | (l1 << 16);
    }
}

// ---------------- bulk-copy pipelined fp16 3-term GEMM (128x160, 3-stage) ----
// stage fetch = 2 cp.async.bulk (A image 16KB, W image 20KB) + mbarrier tx.
// MODE 0: C = t, C2 = relu(t);  MODE 1: C = relu(t + biasM);  MODE 2: relu(t + biasV[n])
template <int MODE>
__global__ __launch_bounds__(256, 2)
void mma_gemm(const uint32_t* __restrict__ Aimg, const uint32_t* __restrict__ Wimg,
              int nKt,
              const float* __restrict__ biasM, const float* __restrict__ biasV,
              float* __restrict__ C, float* __restrict__ C2)
{
    extern __shared__ uint32_t sm[];
    const unsigned sbase = (unsigned)__cvta_generic_to_shared(sm);
    const unsigned mbar0 = sbase + 3 * STAGE_BYTES;

    const int tid  = threadIdx.x;
    const int lane = tid & 31;
    const int wid  = tid >> 5;
    const int wm   = wid & 3;          // 4 warps along M (32 rows each)
    const int wn   = wid >> 2;         // 2 warps along N (80 cols each)
    const int row0 = blockIdx.y * 128;
    const int col0 = blockIdx.x * BN;

    const uint32_t* Ab = Aimg + (size_t)blockIdx.y * nKt * A_IMG;
    const uint32_t* Wb = Wimg + (size_t)blockIdx.x * nKt * W_IMG;

    if (tid == 0) {
#pragma unroll
        for (int s = 0; s < 3; s++)
            asm volatile("mbarrier.init.shared.b64 [%0], 1;" :: "r"(mbar0 + s * 8) : "memory");
    }
    __syncthreads();

    auto issue = [&](int kt) {
        int s = kt % 3;
        unsigned bar = mbar0 + s * 8;
        unsigned d   = sbase + s * STAGE_BYTES;
        asm volatile("mbarrier.arrive.expect_tx.shared.b64 _, [%0], %1;"
                     :: "r"(bar), "r"((unsigned)STAGE_BYTES) : "memory");
        asm volatile(
            "cp.async.bulk.shared::cluster.global.mbarrier::complete_tx::bytes [%0], [%1], %2, [%3];"
            :: "r"(d), "l"(Ab + (size_t)kt * A_IMG), "r"((unsigned)(A_IMG * 4)), "r"(bar)
            : "memory");
        asm volatile(
            "cp.async.bulk.shared::cluster.global.mbarrier::complete_tx::bytes [%0], [%1], %2, [%3];"
            :: "r"(d + A_IMG * 4), "l"(Wb + (size_t)kt * W_IMG), "r"((unsigned)(W_IMG * 4)), "r"(bar)
            : "memory");
    };

    if (tid == 0) { issue(0); issue(1); }      // nKt >= 3 for all layers

    float acc[2][10][4];
#pragma unroll
    for (int a = 0; a < 2; a++)
#pragma unroll
        for (int b = 0; b < 10; b++)
#pragma unroll
            for (int q = 0; q < 4; q++) acc[a][b][q] = 0.f;

    for (int kt = 0; kt < nKt; kt++) {
        mbar_wait(mbar0 + (kt % 3) * 8, (unsigned)((kt / 3) & 1));
        __syncthreads();                        // all warps done with stage kt-1
        if (tid == 0 && kt + 2 < nKt) issue(kt + 2);

        const uint32_t* S = sm + (kt % 3) * STAGE_WORDS;
        const uint32_t* sAhh = S;
        const uint32_t* sAx  = S + 1536;
        const uint32_t* sBhh = S + 4096;
        const uint32_t* sBx  = S + 6016;

        // ---- hh: one k16 MMA covers all 16 original k
        {
            const int kc = lane & 3;
            uint32_t aH[2][4];
#pragma unroll
            for (int mt = 0; mt < 2; mt++) {
                int r = wm * 32 + mt * 16 + (lane >> 2);
                const uint32_t* p = sAhh + r * 12 + kc;
                aH[mt][0] = p[0]; aH[mt][1] = p[96]; aH[mt][2] = p[4]; aH[mt][3] = p[100];
            }
#pragma unroll
            for (int nt = 0; nt < 10; nt++) {
                int n = wn * 80 + nt * 8 + (lane >> 2);
                const uint32_t* p = sBhh + n * 12 + kc;
                uint32_t b0 = p[0], b1 = p[4];
#pragma unroll
                for (int mt = 0; mt < 2; mt++)
                    mma_f16(acc[mt][nt], aH[mt], b0, b1);
            }
        }

        // ---- cross: two k16 MMAs (8 original k each)
#pragma unroll
        for (int ks = 0; ks < 2; ks++) {
            const int kc = ks * 8 + (lane & 3);
            uint32_t aX[2][4];
#pragma unroll
            for (int mt = 0; mt < 2; mt++) {
                int r = wm * 32 + mt * 16 + (lane >> 2);
                const uint32_t* p = sAx + r * 20 + kc;
                aX[mt][0] = p[0]; aX[mt][1] = p[160]; aX[mt][2] = p[4]; aX[mt][3] = p[164];
            }
#pragma unroll
            for (int nt = 0; nt < 10; nt++) {
                int n = wn * 80 + nt * 8 + (lane >> 2);
                const uint32_t* p = sBx + n * 20 + kc;
                uint32_t b0 = p[0], b1 = p[4];
#pragma unroll
                for (int mt = 0; mt < 2; mt++)
                    mma_f16(acc[mt][nt], aX[mt], b0, b1);
            }
        }
    }

    // epilogue (rows padded; cols < 480 <= LDC, padded cols harmless)
#pragma unroll
    for (int mt = 0; mt < 2; mt++) {
#pragma unroll
        for (int h = 0; h < 2; h++) {
            int r = row0 + wm * 32 + mt * 16 + (lane >> 2) + h * 8;
#pragma unroll
            for (int nt = 0; nt < 10; nt++) {
                int c = col0 + wn * 80 + nt * 8 + 2 * (lane & 3);
                float x = acc[mt][nt][h * 2 + 0];
                float y = acc[mt][nt][h * 2 + 1];
                size_t o = (size_t)r * LDC + c;
                if (MODE == 0) {
                    *(float2*)(C + o)  = make_float2(x, y);
                    *(float2*)(C2 + o) = make_float2(x > 0.f ? x : 0.f, y > 0.f ? y : 0.f);
                } else if (MODE == 1) {
                    float2 bm = *(const float2*)(biasM + o);
                    x += bm.x; y += bm.y;
                    *(float2*)(C + o) = make_float2(x > 0.f ? x : 0.f, y > 0.f ? y : 0.f);
                } else {
                    x += (c     < HIDDEN) ? biasV[c]     : 0.f;
                    y += (c + 1 < HIDDEN) ? biasV[c + 1] : 0.f;
                    *(float2*)(C + o) = make_float2(x > 0.f ? x : 0.f, y > 0.f ? y : 0.f);
                }
            }
        }
    }
}

// ---------------- per-molecule mean -----------------------------------------
__global__ __launch_bounds__(256)
void mol_mean_kernel(const float* __restrict__ ah, const int* __restrict__ mol_ids,
                     int n_atoms, float* __restrict__ out)
{
    const int m = blockIdx.x;
    __shared__ int s_start, s_end;
    if (threadIdx.x == 0) {
        int lo = 0, hi = n_atoms;
        while (lo < hi) { int mid = (lo + hi) >> 1; if (mol_ids[mid] <  m) lo = mid + 1; else hi = mid; }
        s_start = lo;
        lo = 0; hi = n_atoms;
        while (lo < hi) { int mid = (lo + hi) >> 1; if (mol_ids[mid] <= m) lo = mid + 1; else hi = mid; }
        s_end = lo;
    }
    __syncthreads();
    const int start = s_start;
    const int cnt   = s_end - s_start;
    const float inv = cnt > 0 ? 1.f / (float)cnt : 0.f;

    for (int h = threadIdx.x; h < HIDDEN; h += blockDim.x) {
        float s = 0.f;
        for (int a = 0; a < cnt; a++)
            s += ah[(size_t)(start + a) * LDC + h];
        out[(size_t)m * HIDDEN + h] = s * inv;
    }
}

// ---------------- launch ----------------------------------------------------
extern "C" void kernel_launch(void* const* d_in, const int* in_sizes, int n_in,
                              void* d_out, int out_size)
{
    const float* fatoms  = (const float*)d_in[0];
    const float* fbonds  = (const float*)d_in[1];
    const int*   agraph  = (const int*)d_in[2];
    const int*   bgraph  = (const int*)d_in[3];
    const int*   mol_ids = (const int*)d_in[4];
    const float* tree    = (const float*)d_in[6];
    const float* W_i     = (const float*)d_in[7];
    const float* W_h     = (const float*)d_in[8];
    const float* W_o     = (const float*)d_in[9];
    const float* b_o     = (const float*)d_in[10];
    float* out = (float*)d_out;

    const int n_atoms = in_sizes[0] / ATOM_FDIM;
    const int n_bonds = in_sizes[1] / (ATOM_FDIM + 5);
    const int n_mess  = in_sizes[6] / HIDDEN;
    const int n_mols  = out_size / HIDDEN;
    const int IN_FDIM = ATOM_FDIM + 5;       // 40
    const int OUT_K   = ATOM_FDIM + HIDDEN;  // 485 (src W_o ld)

    float *binput, *gmsg;
    uint32_t *neiI, *atI, *fbI, *WiI, *WhI, *WoI;
    cudaGetSymbolAddress((void**)&binput, g_binput);
    cudaGetSymbolAddress((void**)&gmsg,   g_gmsg);
    cudaGetSymbolAddress((void**)&neiI,   g_neiI);
    cudaGetSymbolAddress((void**)&atI,    g_atI);
    cudaGetSymbolAddress((void**)&fbI,    g_fbI);
    cudaGetSymbolAddress((void**)&WiI,    g_WiI);
    cudaGetSymbolAddress((void**)&WhI,    g_WhI);
    cudaGetSymbolAddress((void**)&WoI,    g_WoI);

    cudaFuncSetAttribute(mma_gemm<0>, cudaFuncAttributeMaxDynamicSharedMemorySize, SMEM_BYTES);
    cudaFuncSetAttribute(mma_gemm<1>, cudaFuncAttributeMaxDynamicSharedMemorySize, SMEM_BYTES);
    cudaFuncSetAttribute(mma_gemm<2>, cudaFuncAttributeMaxDynamicSharedMemorySize, SMEM_BYTES);

    dim3 blk(256);
    const int mb = (n_bonds + 127) / 128;   // 313
    const int ma = (n_atoms + 127) / 128;   // 157
    dim3 grid_b(NCB, mb), grid_a(NCB, ma);

    // ---- pre-split inputs (SIDE 0) & weights (SIDE 1) into tile-major images
    split_pack<0><<<(n_bonds * ((IN_FDIM + 1) / 2) + 255) / 256, blk>>>(
        fbonds, IN_FDIM, n_bonds, IN_FDIM, fbI, KT_I, 0);
    split_pack<1><<<(HIDDEN * ((IN_FDIM + 1) / 2) + 255) / 256, blk>>>(
        W_i, IN_FDIM, HIDDEN, IN_FDIM, WiI, KT_I, 0);
    split_pack<1><<<(HIDDEN * ((HIDDEN + 1) / 2) + 255) / 256, blk>>>(
        W_h, HIDDEN, HIDDEN, HIDDEN, WhI, KT_B, 0);
    // W_o permuted: [nei 450 | fatoms 35]
    split_pack<1><<<(HIDDEN * ((HIDDEN + 1) / 2) + 255) / 256, blk>>>(
        W_o + ATOM_FDIM, OUT_K, HIDDEN, HIDDEN, WoI, KT_O, 0);
    split_pack<1><<<(HIDDEN * ((ATOM_FDIM + 1) / 2) + 255) / 256, blk>>>(
        W_o, OUT_K, HIDDEN, ATOM_FDIM, WoI, KT_O, HIDDEN);
    // fatoms at k-offset 450
    split_pack<0><<<(n_atoms * ((ATOM_FDIM + 1) / 2) + 255) / 256, blk>>>(
        fatoms, ATOM_FDIM, n_atoms, ATOM_FDIM, atI, KT_O, HIDDEN);

    // ---- init layer: binput = fbonds @ W_i^T ; gmsg = relu(binput)
    mma_gemm<0><<<grid_b, blk, SMEM_BYTES>>>(fbI, WiI, KT_I,
                                             nullptr, nullptr, binput, gmsg);

    // ---- 5 message-passing steps
    for (int it = 0; it < 5; it++) {
        gather_split<<<n_bonds, blk>>>(bgraph, tree, n_mess, gmsg, neiI, KT_B);
        mma_gemm<1><<<grid_b, blk, SMEM_BYTES>>>(neiI, WhI, KT_B,
                                                 binput, nullptr, gmsg, nullptr);
    }

    // ---- atom aggregation (nei at k 0..449) + output layer
    gather_split<<<n_atoms, blk>>>(agraph, tree, n_mess, gmsg, atI, KT_O);
    mma_gemm<2><<<grid_a, blk, SMEM_BYTES>>>(atI, WoI, KT_O,
                                             nullptr, b_o, binput, nullptr);

    // ---- per-molecule mean (atom_hiddens reuses g_binput)
    mol_mean_kernel<<<n_mols, blk>>>(binput, mol_ids, n_atoms, out);
}

// round 17
// speedup vs baseline: 1.2494x; 1.0509x over previous
#include <cuda_runtime.h>
#include <cuda_fp16.h>
#include <cstdint>

#define HIDDEN    450
#define ATOM_FDIM 35
#define MAX_NB    15

#define LDC     512          // fp32 activation stride
#define MB_PAD  40064        // 313*128
#define MA_PAD  20096        // 157*128
#define MB_T    313          // row blocks (bonds)
#define MA_T    157          // row blocks (atoms)
#define NCB     3            // col blocks (3 x 160 = 480 >= 456)
#define KT_B    29           // ktiles, hidden K (464/16)
#define KT_I    3            // ktiles, input K (48/16)
#define KT_O    31           // ktiles, output K (496/16)

#define BN      160
// tile-major images: A image 4096 u32 = Ahh[128][12] | Ax[128][20]
//                    W image 5120 u32 = Bhh[160][12] | Bx[160][20]
#define A_IMG   4096
#define W_IMG   5120
#define STAGE_WORDS 9216                       // A_IMG + W_IMG
#define STAGE_BYTES (STAGE_WORDS * 4)          // 36864
#define SMEM_BYTES  (3 * STAGE_BYTES + 128)    // 3 stages + mbarriers

// ---------------- scratch (device globals; .bss zero => padding zero) --------
__device__ float g_binput[(size_t)MB_PAD * LDC];
__device__ float g_gmsg  [(size_t)MB_PAD * LDC];
__device__ __align__(128) uint32_t g_neiI[(size_t)MB_T * KT_B * A_IMG];
__device__ __align__(128) uint32_t g_atI [(size_t)MA_T * KT_O * A_IMG];
__device__ __align__(128) uint32_t g_fbI [(size_t)MB_T * KT_I * A_IMG];
__device__ __align__(128) uint32_t g_WiI [NCB * KT_I * W_IMG];
__device__ __align__(128) uint32_t g_WhI [NCB * KT_B * W_IMG];
__device__ __align__(128) uint32_t g_WoI [NCB * KT_O * W_IMG];

// ---------------- fp16 split helpers -----------------------------------------
__device__ __forceinline__ void split_h(float v, uint32_t& h, uint32_t& l) {
    __half hh = __float2half_rn(v);
    float  hf = __half2float(hh);
    __half ll = __float2half_rn(v - hf);
    h = (uint32_t)__half_as_ushort(hh);
    l = (uint32_t)__half_as_ushort(ll);
}

__device__ __forceinline__ void mma_f16(float* c, const uint32_t* a, uint32_t b0, uint32_t b1) {
    asm volatile(
        "mma.sync.aligned.m16n8k16.row.col.f32.f16.f16.f32 "
        "{%0,%1,%2,%3},{%4,%5,%6,%7},{%8,%9},{%0,%1,%2,%3};"
        : "+f"(c[0]), "+f"(c[1]), "+f"(c[2]), "+f"(c[3])
        : "r"(a[0]), "r"(a[1]), "r"(a[2]), "r"(a[3]), "r"(b0), "r"(b1));
}

__device__ __forceinline__ void mbar_wait(unsigned bar, unsigned phase) {
    asm volatile(
        "{\n\t.reg .pred P;\n\t"
        "W_%=:\n\t"
        "mbarrier.try_wait.parity.acquire.cta.shared::cta.b64 P, [%0], %1;\n\t"
        "@!P bra W_%=;\n\t"
        "}" :: "r"(bar), "r"(phase) : "memory");
}

// ---------------- pre-split into tile-major images ---------------------------
// SIDE 0 (A image): x-pack = {lo16: hi, hi16: lo}, rows/blk 128
// SIDE 1 (W image): x-pack = {lo16: lo, hi16: hi}, rows/blk 160
template <int SIDE>
__global__ __launch_bounds__(256)
void split_pack(const float* __restrict__ src, int ld_src, int rows, int cols,
                uint32_t* __restrict__ img, int nKt, int dstk0 /* even */)
{
    const int npair = (cols + 1) >> 1;
    int i = blockIdx.x * blockDim.x + threadIdx.x;
    if (i >= rows * npair) return;
    int r = i / npair, jj = i - r * npair;
    int k0 = 2 * jj, k1 = k0 + 1;
    float v0 = src[(size_t)r * ld_src + k0];
    float v1 = (k1 < cols) ? src[(size_t)r * ld_src + k1] : 0.f;
    uint32_t h0, l0, h1, l1;
    split_h(v0, h0, l0);
    split_h(v1, h1, l1);
    int kg = dstk0 + k0;           // global even k
    int kt = kg >> 4, w = kg & 15;
    if (SIDE == 0) {
        int rb = r >> 7, rr = r & 127;
        size_t base = ((size_t)rb * nKt + kt) * A_IMG;
        img[base + rr * 12 + (w >> 1)]        = h0 | (h1 << 16);
        img[base + 1536 + rr * 20 + w]        = h0 | (l0 << 16);
        img[base + 1536 + rr * 20 + w + 1]    = h1 | (l1 << 16);
    } else {
        int cb = r / BN, rr = r - cb * BN;
        size_t base = ((size_t)cb * nKt + kt) * W_IMG;
        img[base + rr * 12 + (w >> 1)]        = h0 | (h1 << 16);
        img[base + 1920 + rr * 20 + w]        = l0 | (h0 << 16);
        img[base + 1920 + rr * 20 + w + 1]    = l1 | (h1 << 16);
    }
}

// ---------------- gather + split into A image --------------------------------
__global__ __launch_bounds__(256)
void gather_split(const int* __restrict__ graph,
                  const float* __restrict__ tree, int n_mess,
                  const float* __restrict__ gmsg,
                  uint32_t* __restrict__ img, int nKt)
{
    const int b = blockIdx.x;
    __shared__ const float* rows[MAX_NB];
    if (threadIdx.x < MAX_NB) {
        int id = graph[(size_t)b * MAX_NB + threadIdx.x];
        rows[threadIdx.x] = (id < n_mess) ? (tree + (size_t)id * HIDDEN)
                                          : (gmsg + (size_t)(id - n_mess) * LDC);
    }
    __syncthreads();
    const int t = threadIdx.x;
    if (t < HIDDEN / 2) {
        float2 acc = make_float2(0.f, 0.f);
#pragma unroll
        for (int nb = 0; nb < MAX_NB; nb++) {
            float2 v = ((const float2*)rows[nb])[t];
            acc.x += v.x; acc.y += v.y;
        }
        uint32_t h0, l0, h1, l1;
        split_h(acc.x, h0, l0);
        split_h(acc.y, h1, l1);
        int kt = t >> 3;                 // ktile of k=2t
        int hw = t & 7;                  // hh word
        int xw = (t & 7) * 2;            // x word
        size_t base = ((size_t)(b >> 7) * nKt + kt) * A_IMG;
        int rr = b & 127;
        img[base + rr * 12 + hw]           = h0 | (h1 << 16);
        img[base + 1536 + rr * 20 + xw]    = h0 | (l0 << 16);
        img[base + 1536 + rr * 20 + xw + 1] = h1 | (l1 << 16);
    }
}

// ---------------- bulk-copy pipelined fp16 3-term GEMM (128x160, 3-stage) ----
// full[s] = tx mbarrier; empty[s] = 8-warp arrive mbarrier (replaces syncthreads)
// MODE 0: C = t, C2 = relu(t);  MODE 1: C = relu(t + biasM);  MODE 2: relu(t + biasV[n])
template <int MODE>
__global__ __launch_bounds__(256, 2)
void mma_gemm(const uint32_t* __restrict__ Aimg, const uint32_t* __restrict__ Wimg,
              int nKt,
              const float* __restrict__ biasM, const float* __restrict__ biasV,
              float* __restrict__ C, float* __restrict__ C2)
{
    extern __shared__ uint32_t sm[];
    const unsigned sbase = (unsigned)__cvta_generic_to_shared(sm);
    const unsigned fullb  = sbase + 3 * STAGE_BYTES;       // 3 x 8B
    const unsigned emptyb = fullb + 24;                    // 3 x 8B

    const int tid  = threadIdx.x;
    const int lane = tid & 31;
    const int wid  = tid >> 5;
    const int wm   = wid & 3;          // 4 warps along M (32 rows each)
    const int wn   = wid >> 2;         // 2 warps along N (80 cols each)
    const int row0 = blockIdx.y * 128;
    const int col0 = blockIdx.x * BN;

    const uint32_t* Ab = Aimg + (size_t)blockIdx.y * nKt * A_IMG;
    const uint32_t* Wb = Wimg + (size_t)blockIdx.x * nKt * W_IMG;

    if (tid == 0) {
#pragma unroll
        for (int s = 0; s < 3; s++) {
            asm volatile("mbarrier.init.shared.b64 [%0], 1;" :: "r"(fullb  + s * 8) : "memory");
            asm volatile("mbarrier.init.shared.b64 [%0], 8;" :: "r"(emptyb + s * 8) : "memory");
        }
    }
    __syncthreads();

    auto issue = [&](int kt) {
        int s = kt % 3;
        unsigned bar = fullb + s * 8;
        unsigned d   = sbase + s * STAGE_BYTES;
        asm volatile("mbarrier.arrive.expect_tx.shared.b64 _, [%0], %1;"
                     :: "r"(bar), "r"((unsigned)STAGE_BYTES) : "memory");
        asm volatile(
            "cp.async.bulk.shared::cluster.global.mbarrier::complete_tx::bytes [%0], [%1], %2, [%3];"
            :: "r"(d), "l"(Ab + (size_t)kt * A_IMG), "r"((unsigned)(A_IMG * 4)), "r"(bar)
            : "memory");
        asm volatile(
            "cp.async.bulk.shared::cluster.global.mbarrier::complete_tx::bytes [%0], [%1], %2, [%3];"
            :: "r"(d + A_IMG * 4), "l"(Wb + (size_t)kt * W_IMG), "r"((unsigned)(W_IMG * 4)), "r"(bar)
            : "memory");
    };

    if (tid == 0) { issue(0); issue(1); }      // nKt >= 3 for all layers

    float acc[2][10][4];
#pragma unroll
    for (int a = 0; a < 2; a++)
#pragma unroll
        for (int b = 0; b < 10; b++)
#pragma unroll
            for (int q = 0; q < 4; q++) acc[a][b][q] = 0.f;

    for (int kt = 0; kt < nKt; kt++) {
        mbar_wait(fullb + (kt % 3) * 8, (unsigned)((kt / 3) & 1));

        if (tid == 0 && kt + 2 < nKt) {
            int j = kt + 2;
            if (j >= 3)   // stage reused: wait for all 8 warps done with ktile j-3
                mbar_wait(emptyb + (j % 3) * 8, (unsigned)(((j / 3) - 1) & 1));
            issue(j);
        }

        const uint32_t* S = sm + (kt % 3) * STAGE_WORDS;
        const uint32_t* sAhh = S;
        const uint32_t* sAx  = S + 1536;
        const uint32_t* sBhh = S + 4096;
        const uint32_t* sBx  = S + 6016;

        // ---- hh: one k16 MMA covers all 16 original k
        {
            const int kc = lane & 3;
            uint32_t aH[2][4];
#pragma unroll
            for (int mt = 0; mt < 2; mt++) {
                int r = wm * 32 + mt * 16 + (lane >> 2);
                const uint32_t* p = sAhh + r * 12 + kc;
                aH[mt][0] = p[0]; aH[mt][1] = p[96]; aH[mt][2] = p[4]; aH[mt][3] = p[100];
            }
#pragma unroll
            for (int nt = 0; nt < 10; nt++) {
                int n = wn * 80 + nt * 8 + (lane >> 2);
                const uint32_t* p = sBhh + n * 12 + kc;
                uint32_t b0 = p[0], b1 = p[4];
#pragma unroll
                for (int mt = 0; mt < 2; mt++)
                    mma_f16(acc[mt][nt], aH[mt], b0, b1);
            }
        }

        // ---- cross: two k16 MMAs (8 original k each)
#pragma unroll
        for (int ks = 0; ks < 2; ks++) {
            const int kc = ks * 8 + (lane & 3);
            uint32_t aX[2][4];
#pragma unroll
            for (int mt = 0; mt < 2; mt++) {
                int r = wm * 32 + mt * 16 + (lane >> 2);
                const uint32_t* p = sAx + r * 20 + kc;
                aX[mt][0] = p[0]; aX[mt][1] = p[160]; aX[mt][2] = p[4]; aX[mt][3] = p[164];
            }
#pragma unroll
            for (int nt = 0; nt < 10; nt++) {
                int n = wn * 80 + nt * 8 + (lane >> 2);
                const uint32_t* p = sBx + n * 20 + kc;
                uint32_t b0 = p[0], b1 = p[4];
#pragma unroll
                for (int mt = 0; mt < 2; mt++)
                    mma_f16(acc[mt][nt], aX[mt], b0, b1);
            }
        }

        // warp done with this stage
        if (lane == 0)
            asm volatile("mbarrier.arrive.shared.b64 _, [%0];"
                         :: "r"(emptyb + (kt % 3) * 8) : "memory");
    }

    // epilogue (rows padded; cols < 480 <= LDC, padded cols harmless)
#pragma unroll
    for (int mt = 0; mt < 2; mt++) {
#pragma unroll
        for (int h = 0; h < 2; h++) {
            int r = row0 + wm * 32 + mt * 16 + (lane >> 2) + h * 8;
#pragma unroll
            for (int nt = 0; nt < 10; nt++) {
                int c = col0 + wn * 80 + nt * 8 + 2 * (lane & 3);
                float x = acc[mt][nt][h * 2 + 0];
                float y = acc[mt][nt][h * 2 + 1];
                size_t o = (size_t)r * LDC + c;
                if (MODE == 0) {
                    *(float2*)(C + o)  = make_float2(x, y);
                    *(float2*)(C2 + o) = make_float2(x > 0.f ? x : 0.f, y > 0.f ? y : 0.f);
                } else if (MODE == 1) {
                    float2 bm = *(const float2*)(biasM + o);
                    x += bm.x; y += bm.y;
                    *(float2*)(C + o) = make_float2(x > 0.f ? x : 0.f, y > 0.f ? y : 0.f);
                } else {
                    x += (c     < HIDDEN) ? biasV[c]     : 0.f;
                    y += (c + 1 < HIDDEN) ? biasV[c + 1] : 0.f;
                    *(float2*)(C + o) = make_float2(x > 0.f ? x : 0.f, y > 0.f ? y : 0.f);
                }
            }
        }
    }
}

// ---------------- per-molecule mean -----------------------------------------
__global__ __launch_bounds__(256)
void mol_mean_kernel(const float* __restrict__ ah, const int* __restrict__ mol_ids,
                     int n_atoms, float* __restrict__ out)
{
    const int m = blockIdx.x;
    __shared__ int s_start, s_end;
    if (threadIdx.x == 0) {
        int lo = 0, hi = n_atoms;
        while (lo < hi) { int mid = (lo + hi) >> 1; if (mol_ids[mid] <  m) lo = mid + 1; else hi = mid; }
        s_start = lo;
        lo = 0; hi = n_atoms;
        while (lo < hi) { int mid = (lo + hi) >> 1; if (mol_ids[mid] <= m) lo = mid + 1; else hi = mid; }
        s_end = lo;
    }
    __syncthreads();
    const int start = s_start;
    const int cnt   = s_end - s_start;
    const float inv = cnt > 0 ? 1.f / (float)cnt : 0.f;

    for (int h = threadIdx.x; h < HIDDEN; h += blockDim.x) {
        float s = 0.f;
        for (int a = 0; a < cnt; a++)
            s += ah[(size_t)(start + a) * LDC + h];
        out[(size_t)m * HIDDEN + h] = s * inv;
    }
}

// ---------------- launch ----------------------------------------------------
extern "C" void kernel_launch(void* const* d_in, const int* in_sizes, int n_in,
                              void* d_out, int out_size)
{
    const float* fatoms  = (const float*)d_in[0];
    const float* fbonds  = (const float*)d_in[1];
    const int*   agraph  = (const int*)d_in[2];
    const int*   bgraph  = (const int*)d_in[3];
    const int*   mol_ids = (const int*)d_in[4];
    const float* tree    = (const float*)d_in[6];
    const float* W_i     = (const float*)d_in[7];
    const float* W_h     = (const float*)d_in[8];
    const float* W_o     = (const float*)d_in[9];
    const float* b_o     = (const float*)d_in[10];
    float* out = (float*)d_out;

    const int n_atoms = in_sizes[0] / ATOM_FDIM;
    const int n_bonds = in_sizes[1] / (ATOM_FDIM + 5);
    const int n_mess  = in_sizes[6] / HIDDEN;
    const int n_mols  = out_size / HIDDEN;
    const int IN_FDIM = ATOM_FDIM + 5;       // 40
    const int OUT_K   = ATOM_FDIM + HIDDEN;  // 485 (src W_o ld)

    float *binput, *gmsg;
    uint32_t *neiI, *atI, *fbI, *WiI, *WhI, *WoI;
    cudaGetSymbolAddress((void**)&binput, g_binput);
    cudaGetSymbolAddress((void**)&gmsg,   g_gmsg);
    cudaGetSymbolAddress((void**)&neiI,   g_neiI);
    cudaGetSymbolAddress((void**)&atI,    g_atI);
    cudaGetSymbolAddress((void**)&fbI,    g_fbI);
    cudaGetSymbolAddress((void**)&WiI,    g_WiI);
    cudaGetSymbolAddress((void**)&WhI,    g_WhI);
    cudaGetSymbolAddress((void**)&WoI,    g_WoI);

    cudaFuncSetAttribute(mma_gemm<0>, cudaFuncAttributeMaxDynamicSharedMemorySize, SMEM_BYTES);
    cudaFuncSetAttribute(mma_gemm<1>, cudaFuncAttributeMaxDynamicSharedMemorySize, SMEM_BYTES);
    cudaFuncSetAttribute(mma_gemm<2>, cudaFuncAttributeMaxDynamicSharedMemorySize, SMEM_BYTES);

    dim3 blk(256);
    const int mb = (n_bonds + 127) / 128;   // 313
    const int ma = (n_atoms + 127) / 128;   // 157
    dim3 grid_b(NCB, mb), grid_a(NCB, ma);

    // ---- pre-split inputs (SIDE 0) & weights (SIDE 1) into tile-major images
    split_pack<0><<<(n_bonds * ((IN_FDIM + 1) / 2) + 255) / 256, blk>>>(
        fbonds, IN_FDIM, n_bonds, IN_FDIM, fbI, KT_I, 0);
    split_pack<1><<<(HIDDEN * ((IN_FDIM + 1) / 2) + 255) / 256, blk>>>(
        W_i, IN_FDIM, HIDDEN, IN_FDIM, WiI, KT_I, 0);
    split_pack<1><<<(HIDDEN * ((HIDDEN + 1) / 2) + 255) / 256, blk>>>(
        W_h, HIDDEN, HIDDEN, HIDDEN, WhI, KT_B, 0);
    // W_o permuted: [nei 450 | fatoms 35]
    split_pack<1><<<(HIDDEN * ((HIDDEN + 1) / 2) + 255) / 256, blk>>>(
        W_o + ATOM_FDIM, OUT_K, HIDDEN, HIDDEN, WoI, KT_O, 0);
    split_pack<1><<<(HIDDEN * ((ATOM_FDIM + 1) / 2) + 255) / 256, blk>>>(
        W_o, OUT_K, HIDDEN, ATOM_FDIM, WoI, KT_O, HIDDEN);
    // fatoms at k-offset 450
    split_pack<0><<<(n_atoms * ((ATOM_FDIM + 1) / 2) + 255) / 256, blk>>>(
        fatoms, ATOM_FDIM, n_atoms, ATOM_FDIM, atI, KT_O, HIDDEN);

    // ---- init layer: binput = fbonds @ W_i^T ; gmsg = relu(binput)
    mma_gemm<0><<<grid_b, blk, SMEM_BYTES>>>(fbI, WiI, KT_I,
                                             nullptr, nullptr, binput, gmsg);

    // ---- 5 message-passing steps
    for (int it = 0; it < 5; it++) {
        gather_split<<<n_bonds, blk>>>(bgraph, tree, n_mess, gmsg, neiI, KT_B);
        mma_gemm<1><<<grid_b, blk, SMEM_BYTES>>>(neiI, WhI, KT_B,
                                                 binput, nullptr, gmsg, nullptr);
    }

    // ---- atom aggregation (nei at k 0..449) + output layer
    gather_split<<<n_atoms, blk>>>(agraph, tree, n_mess, gmsg, atI, KT_O);
    mma_gemm<2><<<grid_a, blk, SMEM_BYTES>>>(atI, WoI, KT_O,
                                             nullptr, b_o, binput, nullptr);

    // ---- per-molecule mean (atom_hiddens reuses g_binput)
    mol_mean_kernel<<<n_mols, blk>>>(binput, mol_ids, n_atoms, out);
}